// round 14
// baseline (speedup 1.0000x reference)
#include <cuda_runtime.h>
#include <cstdint>
#include <math.h>

#define B_DIM 128
#define S_DIM 512
#define IN_DIM 128
#define D_DIM 64
#define G_DIM 256   // 4*D
#define TILE_R 64
#define HPAD 68     // padded row stride for LN smem tile

typedef unsigned long long ull;

// ---- packed f32x2 helpers ----
__device__ __forceinline__ void ffma2(ull& a, ull x, ull y) {
    asm("fma.rn.f32x2 %0, %1, %2, %0;" : "+l"(a) : "l"(x), "l"(y));
}
__device__ __forceinline__ ull addf2(ull x, ull y) {
    ull r; asm("add.rn.f32x2 %0, %1, %2;" : "=l"(r) : "l"(x), "l"(y)); return r;
}
__device__ __forceinline__ ull packf2(float lo, float hi) {
    ull r; asm("mov.b64 %0, {%1, %2};" : "=l"(r) : "f"(lo), "f"(hi)); return r;
}
__device__ __forceinline__ float2 unpackf2(ull v) {
    float2 f; asm("mov.b64 {%0, %1}, %2;" : "=f"(f.x), "=f"(f.y) : "l"(v)); return f;
}
__device__ __forceinline__ void cp_async16(uint32_t smem_addr, const void* gptr) {
    asm volatile("cp.async.ca.shared.global [%0], [%1], 16;\n"
                 :: "r"(smem_addr), "l"(gptr) : "memory");
}
__device__ __forceinline__ void cp_commit() {
    asm volatile("cp.async.commit_group;\n" ::: "memory");
}
__device__ __forceinline__ void cp_wait2() {
    asm volatile("cp.async.wait_group 2;\n" ::: "memory");
}

// Scratch (sanctioned __device__ globals)
__device__ float g_xs [(size_t)S_DIM * B_DIM * G_DIM];   // [s][b][4D]
__device__ float g_Wc [IN_DIM * G_DIM];
__device__ float g_bc [G_DIM];
__device__ float g_h  [(size_t)B_DIM * S_DIM * D_DIM];   // raw h (pre-LN)
__device__ float g_hso[(size_t)B_DIM * S_DIM * D_DIM];   // normalized
__device__ float g_k  [(size_t)B_DIM * S_DIM * D_DIM];
__device__ float g_v  [(size_t)B_DIM * S_DIM * D_DIM];
__device__ float g_im [(size_t)B_DIM * S_DIM];
__device__ float g_fm [(size_t)B_DIM * S_DIM];

// ---------------------------------------------------------------------------
// Kernel 1: fold input projection into sLSTM input weights.
// ---------------------------------------------------------------------------
__global__ void combine_weights(const float* __restrict__ W_in,
                                const float* __restrict__ b_in,
                                const float* __restrict__ W_s,
                                const float* __restrict__ b_s) {
    int j = threadIdx.x;
    int d = blockIdx.x;
    if (d < IN_DIM) {
        float acc = 0.f;
#pragma unroll
        for (int e = 0; e < D_DIM; e++)
            acc += W_in[d * D_DIM + e] * W_s[e * G_DIM + j];
        g_Wc[d * G_DIM + j] = acc;
    } else {
        float acc = b_s[j];
#pragma unroll
        for (int e = 0; e < D_DIM; e++)
            acc += b_in[e] * W_s[e * G_DIM + j];
        g_bc[j] = acc;
    }
}

// ---------------------------------------------------------------------------
// Kernel 2: xs = x @ W_comb + b_comb  (unchanged)
// ---------------------------------------------------------------------------
__global__ __launch_bounds__(256) void xs_gemm(const float* __restrict__ x) {
    __shared__ __align__(16) float xsm[TILE_R][IN_DIM];
    int t = threadIdx.x;
    int row0 = blockIdx.x * TILE_R;

    const float4* xg = reinterpret_cast<const float4*>(x + (size_t)row0 * IN_DIM);
    float4* xs4 = reinterpret_cast<float4*>(&xsm[0][0]);
#pragma unroll
    for (int i = 0; i < (TILE_R * IN_DIM / 4) / 256; i++)
        xs4[t + i * 256] = xg[t + i * 256];

    ull w2[64];
#pragma unroll
    for (int i = 0; i < 64; i++)
        w2[i] = packf2(g_Wc[(2 * i) * G_DIM + t], g_Wc[(2 * i + 1) * G_DIM + t]);
    float bc = g_bc[t];
    __syncthreads();

    for (int r = 0; r < TILE_R; r += 4) {
        ull a0 = 0, a1 = 0, a2 = 0, a3 = 0;
        const ulonglong2* p0 = reinterpret_cast<const ulonglong2*>(xsm[r + 0]);
        const ulonglong2* p1 = reinterpret_cast<const ulonglong2*>(xsm[r + 1]);
        const ulonglong2* p2 = reinterpret_cast<const ulonglong2*>(xsm[r + 2]);
        const ulonglong2* p3 = reinterpret_cast<const ulonglong2*>(xsm[r + 3]);
#pragma unroll
        for (int dq = 0; dq < 32; dq++) {
            ulonglong2 v0 = p0[dq]; ffma2(a0, v0.x, w2[2*dq]); ffma2(a0, v0.y, w2[2*dq+1]);
            ulonglong2 v1 = p1[dq]; ffma2(a1, v1.x, w2[2*dq]); ffma2(a1, v1.y, w2[2*dq+1]);
            ulonglong2 v2 = p2[dq]; ffma2(a2, v2.x, w2[2*dq]); ffma2(a2, v2.y, w2[2*dq+1]);
            ulonglong2 v3 = p3[dq]; ffma2(a3, v3.x, w2[2*dq]); ffma2(a3, v3.y, w2[2*dq+1]);
        }
#pragma unroll
        for (int rr = 0; rr < 4; rr++) {
            ull av = (rr == 0) ? a0 : (rr == 1) ? a1 : (rr == 2) ? a2 : a3;
            float2 f = unpackf2(av);
            int row = row0 + r + rr;
            int bb = row >> 9;
            int ss = row & 511;
            g_xs[((size_t)ss * B_DIM + bb) * G_DIM + t] = f.x + f.y + bc;
        }
    }
}

// ---------------------------------------------------------------------------
// Kernel 3: sequential core, TWO batches per CTA (shared weights, interleaved
// independent chains fill each other's latency). cp.async ring per batch;
// warps 0-3 feed the rings. One __syncthreads per step.
// ---------------------------------------------------------------------------
__global__ __launch_bounds__(256) void recur6(const float* __restrict__ R_s)
{
    __shared__ __align__(16) float hs2[2][2][64];     // [batch][parity][dim]
    __shared__ __align__(16) float xbuf[2][4][G_DIM]; // [batch][stage][col] 8KB

    int t = threadIdx.x;
    int b0 = blockIdx.x * 2;
    int l = t & 31, w = t >> 5;
    int gt = l >> 3;             // gate type: 0=z,1=i,2=f,3=o
    int base = l & 7;
    int dim = (w << 3) + base;   // owned hidden dim
    int col = gt * 64 + dim;     // column in R_s / xs

    ull R2[32];
#pragma unroll
    for (int i = 0; i < 32; i++)
        R2[i] = packf2(R_s[(2 * i) * G_DIM + col], R_s[(2 * i + 1) * G_DIM + col]);

    float alpha, ce, cr, c0;
    if (gt == 0)      { alpha = -2.f; ce = 0.f; cr = 2.f; c0 = -1.f; }  // tanh
    else if (gt == 1) { alpha =  1.f; ce = 1.f; cr = 0.f; c0 =  0.f; }  // exp
    else              { alpha = -1.f; ce = 0.f; cr = 1.f; c0 =  0.f; }  // sigmoid

    float cs0 = 0.f, ns0 = 1.f, cs1 = 0.f, ns1 = 1.f;
    if (t < 64) { hs2[0][1][t] = 0.f; hs2[1][1][t] = 0.f; }

    const size_t BG = (size_t)B_DIM * G_DIM;
    const float* xb0 = g_xs + (size_t)b0 * G_DIM;
    const float* xb1 = g_xs + (size_t)(b0 + 1) * G_DIM;
    uint32_t xs_s = (uint32_t)__cvta_generic_to_shared(&xbuf[0][0][0]);

    // prime stages 0..2: threads 0-63 feed batch0, 64-127 feed batch1
    if (t < 128) {
        int bb = t >> 6;
        int tt = t & 63;
        const float* xb = bb ? xb1 : xb0;
#pragma unroll
        for (int p = 0; p < 3; p++) {
            cp_async16(xs_s + (bb * 4 + p) * (G_DIM * 4) + tt * 16,
                       xb + (size_t)p * BG + tt * 4);
            cp_commit();
        }
        cp_wait2();
    }
    __syncthreads();

    float* hout0 = g_h + (size_t)b0 * S_DIM * D_DIM;
    float* hout1 = g_h + (size_t)(b0 + 1) * S_DIM * D_DIM;

    for (int s = 0; s < S_DIM; s++) {
        // ---- A(s) for both batches (independent chains) ----
        float gv0 = xbuf[0][s & 3][col];
        float gv1 = xbuf[1][s & 3][col];
        {
            const ulonglong2* h20 = reinterpret_cast<const ulonglong2*>(hs2[0][(s + 1) & 1]);
            const ulonglong2* h21 = reinterpret_cast<const ulonglong2*>(hs2[1][(s + 1) & 1]);
            ull a0 = 0, a1 = 0, b0a = 0, b1a = 0;
#pragma unroll
            for (int q = 0; q < 8; q++) {
                ulonglong2 u0 = h20[2 * q];
                ulonglong2 v0 = h20[2 * q + 1];
                ffma2(a0, u0.x, R2[4 * q]);
                ffma2(a1, u0.y, R2[4 * q + 1]);
                ffma2(a0, v0.x, R2[4 * q + 2]);
                ffma2(a1, v0.y, R2[4 * q + 3]);
                ulonglong2 u1 = h21[2 * q];
                ulonglong2 v1 = h21[2 * q + 1];
                ffma2(b0a, u1.x, R2[4 * q]);
                ffma2(b1a, u1.y, R2[4 * q + 1]);
                ffma2(b0a, v1.x, R2[4 * q + 2]);
                ffma2(b1a, v1.y, R2[4 * q + 3]);
            }
            a0 = addf2(a0, a1);
            b0a = addf2(b0a, b1a);
            float2 p0 = unpackf2(a0);
            float2 p1 = unpackf2(b0a);
            gv0 += p0.x + p0.y;
            gv1 += p1.x + p1.y;
        }
        float u0 = __expf(alpha * gv0);
        float u1 = __expf(alpha * gv1);
        float act0 = ce * u0 + cr * __fdividef(1.f, 1.f + u0) + c0;
        float act1 = ce * u1 + cr * __fdividef(1.f, 1.f + u1) + c0;

        // ---- B(s): intra-warp gate exchange + state update, both batches ----
        float z0  = __shfl_sync(0xffffffffu, act0, base);
        float ig0 = __shfl_sync(0xffffffffu, act0, 8 + base);
        float f0  = __shfl_sync(0xffffffffu, act0, 16 + base);
        float o0  = __shfl_sync(0xffffffffu, act0, 24 + base);
        float z1  = __shfl_sync(0xffffffffu, act1, base);
        float ig1 = __shfl_sync(0xffffffffu, act1, 8 + base);
        float f1  = __shfl_sync(0xffffffffu, act1, 16 + base);
        float o1  = __shfl_sync(0xffffffffu, act1, 24 + base);
        cs0 = f0 * cs0 + ig0 * z0;  ns0 = f0 * ns0 + ig0;
        cs1 = f1 * cs1 + ig1 * z1;  ns1 = f1 * ns1 + ig1;
        float h0 = __fdividef(o0 * cs0, ns0);
        float h1 = __fdividef(o1 * cs1, ns1);
        if (l < 8) {
            hs2[0][s & 1][dim] = h0;
            hs2[1][s & 1][dim] = h1;
            hout0[s * D_DIM + dim] = h0;
            hout1[s * D_DIM + dim] = h1;
        }

        // ---- prefetch step s+3 (own batch); stage s+1 guaranteed complete ----
        if (t < 128) {
            int bb = t >> 6;
            int tt = t & 63;
            const float* xb = bb ? xb1 : xb0;
            int sn = (s + 3 < S_DIM) ? (s + 3) : (S_DIM - 1);
            cp_async16(xs_s + (bb * 4 + ((s + 3) & 3)) * (G_DIM * 4) + tt * 16,
                       xb + (size_t)sn * BG + tt * 4);
            cp_commit();
            cp_wait2();
        }
        __syncthreads();
    }
}

// ---------------------------------------------------------------------------
// Kernel 4: LN + k/v projections + im/fm logits (unchanged).
// ---------------------------------------------------------------------------
__global__ __launch_bounds__(256) void projln(
    const float* __restrict__ Wk, const float* __restrict__ Wv,
    const float* __restrict__ ln_g, const float* __restrict__ ln_b,
    const float* __restrict__ wi, const float* __restrict__ bi_p,
    const float* __restrict__ wf, const float* __restrict__ bf_p)
{
    __shared__ __align__(16) float hsm[64][HPAD];
    __shared__ float lng[64], lnb[64], wis[64], wfs[64];
    int t = threadIdx.x;
    size_t row0 = (size_t)blockIdx.x * 64;

    {
        const float4* hg = reinterpret_cast<const float4*>(g_h + row0 * D_DIM);
#pragma unroll
        for (int i = 0; i < 4; i++) {
            int idx = t + i * 256;
            int row = idx >> 4, c4 = idx & 15;
            *reinterpret_cast<float4*>(&hsm[row][c4 * 4]) = hg[idx];
        }
    }
    if (t < 64) { lng[t] = ln_g[t]; lnb[t] = ln_b[t]; wis[t] = wi[t]; wfs[t] = wf[t]; }
    __syncthreads();

    {
        int row = t >> 2, q = t & 3;
        float s1 = 0.f, s2 = 0.f;
#pragma unroll
        for (int e4 = 0; e4 < 4; e4++) {
            float4 v = *reinterpret_cast<float4*>(&hsm[row][q * 16 + e4 * 4]);
            s1 += v.x + v.y + v.z + v.w;
            s2 += v.x * v.x + v.y * v.y + v.z * v.z + v.w * v.w;
        }
        s1 += __shfl_xor_sync(0xffffffffu, s1, 1);
        s2 += __shfl_xor_sync(0xffffffffu, s2, 1);
        s1 += __shfl_xor_sync(0xffffffffu, s1, 2);
        s2 += __shfl_xor_sync(0xffffffffu, s2, 2);
        float mu  = s1 * 0.015625f;
        float inv = rsqrtf(s2 * 0.015625f - mu * mu + 1e-5f);
#pragma unroll
        for (int e4 = 0; e4 < 4; e4++) {
            int c = q * 16 + e4 * 4;
            float4 v = *reinterpret_cast<float4*>(&hsm[row][c]);
            v.x = (v.x - mu) * inv * lng[c]     + lnb[c];
            v.y = (v.y - mu) * inv * lng[c + 1] + lnb[c + 1];
            v.z = (v.z - mu) * inv * lng[c + 2] + lnb[c + 2];
            v.w = (v.w - mu) * inv * lng[c + 3] + lnb[c + 3];
            *reinterpret_cast<float4*>(&hsm[row][c]) = v;
        }
    }
    __syncthreads();

    {
        float4* og = reinterpret_cast<float4*>(g_hso + row0 * D_DIM);
#pragma unroll
        for (int i = 0; i < 4; i++) {
            int idx = t + i * 256;
            int row = idx >> 4, c4 = idx & 15;
            og[idx] = *reinterpret_cast<float4*>(&hsm[row][c4 * 4]);
        }
    }

    if (t < 64) {
        float pi = bi_p[0], pf = bf_p[0];
#pragma unroll 8
        for (int d = 0; d < 64; d++) {
            float h = hsm[t][d];
            pi += h * wis[d];
            pf += h * wfs[d];
        }
        g_im[row0 + t] = __expf(pi);
        g_fm[row0 + t] = __fdividef(1.f, 1.f + __expf(-pf));
    }

    int rg = t >> 7;
    int col = t & 127;
    const float* Wsel = (col < 64) ? Wk : Wv;
    const int c = col & 63;
    ull W2[32];
#pragma unroll
    for (int i = 0; i < 32; i++)
        W2[i] = packf2(Wsel[(2 * i) * 64 + c], Wsel[(2 * i + 1) * 64 + c]);
    float scale = (col < 64) ? 0.125f : 1.f;
    float* outp = (col < 64) ? g_k : g_v;

    for (int r = 0; r < 32; r += 2) {
        int row = rg * 32 + r;
        ull a0 = 0, a1 = 0, b0 = 0, b1 = 0;
        const ulonglong2* h0 = reinterpret_cast<const ulonglong2*>(hsm[row]);
        const ulonglong2* h1 = reinterpret_cast<const ulonglong2*>(hsm[row + 1]);
#pragma unroll
        for (int q = 0; q < 16; q++) {
            ulonglong2 u = h0[q];
            ffma2(a0, u.x, W2[2 * q]);
            ffma2(a1, u.y, W2[2 * q + 1]);
            ulonglong2 v = h1[q];
            ffma2(b0, v.x, W2[2 * q]);
            ffma2(b1, v.y, W2[2 * q + 1]);
        }
        a0 = addf2(a0, a1); b0 = addf2(b0, b1);
        float2 fa = unpackf2(a0);
        float2 fb = unpackf2(b0);
        outp[(row0 + row) * 64 + c]     = (fa.x + fa.y) * scale;
        outp[(row0 + row + 1) * 64 + c] = (fb.x + fb.y) * scale;
    }
}

// ---------------------------------------------------------------------------
// Kernel 5: per-batch suffix-product scan + weighted sums + fusion gate.
// ---------------------------------------------------------------------------
__global__ __launch_bounds__(64) void scan2(
    const float* __restrict__ Wq,
    const float* __restrict__ Wo, const float* __restrict__ bo,
    const float* __restrict__ W_fuse, const float* __restrict__ b_fuse,
    float* __restrict__ out)
{
    __shared__ float hlast[64], qv[64], omv[64], hm[64];
    __shared__ float fmv[512], cp[512], av[512];

    int t = threadIdx.x;
    int b = blockIdx.x;
    const float* hso_b = g_hso + (size_t)b * S_DIM * D_DIM;

    hlast[t] = hso_b[511 * 64 + t];
    for (int s = t; s < S_DIM; s += 64) fmv[s] = g_fm[(size_t)b * S_DIM + s];
    __syncthreads();

    {
        float aq = 0.f, ao = bo[t];
#pragma unroll 8
        for (int d = 0; d < 64; d++) {
            float h = hlast[d];
            aq += h * Wq[d * 64 + t];
            ao += h * Wo[d * 64 + t];
        }
        qv[t] = aq;
        omv[t] = __fdividef(1.f, 1.f + __expf(-ao));
    }
    __syncthreads();

    if (t == 0) {
        float c = 1.f;
        cp[511] = 1.f;
        for (int s = 510; s >= 0; s--) { c *= fmv[s + 1]; cp[s] = c; }
    }
    __syncthreads();

    const float* kb = g_k + (size_t)b * S_DIM * D_DIM;
    for (int s = t; s < S_DIM; s += 64) {
        const float4* kr = reinterpret_cast<const float4*>(kb + s * 64);
        float kq = 0.f;
#pragma unroll
        for (int d4 = 0; d4 < 16; d4++) {
            float4 kv = kr[d4];
            kq += kv.x * qv[d4*4] + kv.y * qv[d4*4+1] + kv.z * qv[d4*4+2] + kv.w * qv[d4*4+3];
        }
        av[s] = g_im[(size_t)b * S_DIM + s] * cp[s] * kq;
    }
    __syncthreads();

    const float* vb = g_v + (size_t)b * S_DIM * D_DIM;
    float num = 0.f, den = 0.f;
#pragma unroll 4
    for (int s = 0; s < S_DIM; s++) {
        float a = av[s];
        num += a * vb[s * 64 + t];
        den += a;
    }
    den = fmaxf(fabsf(den), 1.f);
    hm[t] = omv[t] * num / den;
    __syncthreads();

    float gp = b_fuse[t];
#pragma unroll 8
    for (int r = 0; r < 64; r++) gp += hlast[r] * W_fuse[r * 64 + t];
#pragma unroll 8
    for (int r = 0; r < 64; r++) gp += hm[r] * W_fuse[(64 + r) * 64 + t];
    float gate = __fdividef(1.f, 1.f + __expf(-gp));
    out[b * 64 + t] = gate * hm[t] + (1.f - gate) * hlast[t];
}

// ---------------------------------------------------------------------------
extern "C" void kernel_launch(void* const* d_in, const int* in_sizes, int n_in,
                              void* d_out, int out_size) {
    const float* x      = (const float*)d_in[0];
    const float* W_in   = (const float*)d_in[1];
    const float* b_in   = (const float*)d_in[2];
    const float* W_s    = (const float*)d_in[3];
    const float* R_s    = (const float*)d_in[4];
    const float* b_s    = (const float*)d_in[5];
    const float* ln_g   = (const float*)d_in[6];
    const float* ln_b   = (const float*)d_in[7];
    const float* Wq     = (const float*)d_in[8];
    const float* Wk     = (const float*)d_in[9];
    const float* Wv     = (const float*)d_in[10];
    const float* wi     = (const float*)d_in[11];
    const float* bi     = (const float*)d_in[12];
    const float* wf     = (const float*)d_in[13];
    const float* bf     = (const float*)d_in[14];
    const float* Wo     = (const float*)d_in[15];
    const float* bo     = (const float*)d_in[16];
    const float* W_fuse = (const float*)d_in[17];
    const float* b_fuse = (const float*)d_in[18];
    float* out = (float*)d_out;

    combine_weights<<<IN_DIM + 1, G_DIM>>>(W_in, b_in, W_s, b_s);
    xs_gemm<<<(B_DIM * S_DIM) / TILE_R, 256>>>(x);
    recur6<<<B_DIM / 2, 256>>>(R_s);
    projln<<<(B_DIM * S_DIM) / 64, 256>>>(Wk, Wv, ln_g, ln_b, wi, bi, wf, bf);
    scan2<<<B_DIM, 64>>>(Wq, Wo, bo, W_fuse, b_fuse, out);
}

// round 15
// speedup vs baseline: 1.2587x; 1.2587x over previous
#include <cuda_runtime.h>
#include <cstdint>
#include <math.h>

#define B_DIM 128
#define S_DIM 512
#define IN_DIM 128
#define D_DIM 64
#define G_DIM 256   // 4*D
#define TILE_R 64
#define HPAD 68     // padded row stride for LN smem tile

typedef unsigned long long ull;

// ---- packed f32x2 helpers ----
__device__ __forceinline__ void ffma2(ull& a, ull x, ull y) {
    asm("fma.rn.f32x2 %0, %1, %2, %0;" : "+l"(a) : "l"(x), "l"(y));
}
__device__ __forceinline__ ull addf2(ull x, ull y) {
    ull r; asm("add.rn.f32x2 %0, %1, %2;" : "=l"(r) : "l"(x), "l"(y)); return r;
}
__device__ __forceinline__ ull packf2(float lo, float hi) {
    ull r; asm("mov.b64 %0, {%1, %2};" : "=l"(r) : "f"(lo), "f"(hi)); return r;
}
__device__ __forceinline__ float2 unpackf2(ull v) {
    float2 f; asm("mov.b64 {%0, %1}, %2;" : "=f"(f.x), "=f"(f.y) : "l"(v)); return f;
}
__device__ __forceinline__ void cp_async4(uint32_t smem_addr, const void* gptr) {
    asm volatile("cp.async.ca.shared.global [%0], [%1], 4;\n"
                 :: "r"(smem_addr), "l"(gptr) : "memory");
}
__device__ __forceinline__ void cp_commit() {
    asm volatile("cp.async.commit_group;\n" ::: "memory");
}
__device__ __forceinline__ void cp_wait2() {
    asm volatile("cp.async.wait_group 2;\n" ::: "memory");
}

// Scratch (sanctioned __device__ globals)
__device__ float g_xs [(size_t)S_DIM * B_DIM * G_DIM];   // [s][b][4D]
__device__ float g_Wc [IN_DIM * G_DIM];
__device__ float g_bc [G_DIM];
__device__ float g_h  [(size_t)B_DIM * S_DIM * D_DIM];   // raw h (pre-LN)
__device__ float g_hso[(size_t)B_DIM * S_DIM * D_DIM];   // normalized
__device__ float g_k  [(size_t)B_DIM * S_DIM * D_DIM];
__device__ float g_v  [(size_t)B_DIM * S_DIM * D_DIM];
__device__ float g_im [(size_t)B_DIM * S_DIM];
__device__ float g_fm [(size_t)B_DIM * S_DIM];

// ---------------------------------------------------------------------------
// Kernel 1: fold input projection into sLSTM input weights.
// ---------------------------------------------------------------------------
__global__ void combine_weights(const float* __restrict__ W_in,
                                const float* __restrict__ b_in,
                                const float* __restrict__ W_s,
                                const float* __restrict__ b_s) {
    int j = threadIdx.x;
    int d = blockIdx.x;
    if (d < IN_DIM) {
        float acc = 0.f;
#pragma unroll
        for (int e = 0; e < D_DIM; e++)
            acc += W_in[d * D_DIM + e] * W_s[e * G_DIM + j];
        g_Wc[d * G_DIM + j] = acc;
    } else {
        float acc = b_s[j];
#pragma unroll
        for (int e = 0; e < D_DIM; e++)
            acc += b_in[e] * W_s[e * G_DIM + j];
        g_bc[j] = acc;
    }
}

// ---------------------------------------------------------------------------
// Kernel 2: xs = x @ W_comb + b_comb  (unchanged)
// ---------------------------------------------------------------------------
__global__ __launch_bounds__(256) void xs_gemm(const float* __restrict__ x) {
    __shared__ __align__(16) float xsm[TILE_R][IN_DIM];
    int t = threadIdx.x;
    int row0 = blockIdx.x * TILE_R;

    const float4* xg = reinterpret_cast<const float4*>(x + (size_t)row0 * IN_DIM);
    float4* xs4 = reinterpret_cast<float4*>(&xsm[0][0]);
#pragma unroll
    for (int i = 0; i < (TILE_R * IN_DIM / 4) / 256; i++)
        xs4[t + i * 256] = xg[t + i * 256];

    ull w2[64];
#pragma unroll
    for (int i = 0; i < 64; i++)
        w2[i] = packf2(g_Wc[(2 * i) * G_DIM + t], g_Wc[(2 * i + 1) * G_DIM + t]);
    float bc = g_bc[t];
    __syncthreads();

    for (int r = 0; r < TILE_R; r += 4) {
        ull a0 = 0, a1 = 0, a2 = 0, a3 = 0;
        const ulonglong2* p0 = reinterpret_cast<const ulonglong2*>(xsm[r + 0]);
        const ulonglong2* p1 = reinterpret_cast<const ulonglong2*>(xsm[r + 1]);
        const ulonglong2* p2 = reinterpret_cast<const ulonglong2*>(xsm[r + 2]);
        const ulonglong2* p3 = reinterpret_cast<const ulonglong2*>(xsm[r + 3]);
#pragma unroll
        for (int dq = 0; dq < 32; dq++) {
            ulonglong2 v0 = p0[dq]; ffma2(a0, v0.x, w2[2*dq]); ffma2(a0, v0.y, w2[2*dq+1]);
            ulonglong2 v1 = p1[dq]; ffma2(a1, v1.x, w2[2*dq]); ffma2(a1, v1.y, w2[2*dq+1]);
            ulonglong2 v2 = p2[dq]; ffma2(a2, v2.x, w2[2*dq]); ffma2(a2, v2.y, w2[2*dq+1]);
            ulonglong2 v3 = p3[dq]; ffma2(a3, v3.x, w2[2*dq]); ffma2(a3, v3.y, w2[2*dq+1]);
        }
#pragma unroll
        for (int rr = 0; rr < 4; rr++) {
            ull av = (rr == 0) ? a0 : (rr == 1) ? a1 : (rr == 2) ? a2 : a3;
            float2 f = unpackf2(av);
            int row = row0 + r + rr;
            int bb = row >> 9;
            int ss = row & 511;
            g_xs[((size_t)ss * B_DIM + bb) * G_DIM + t] = f.x + f.y + bc;
        }
    }
}

// ---------------------------------------------------------------------------
// Kernel 3: sequential core (R13) with cp.async spread over ALL 8 warps:
// each of the 256 threads loads its own 4 bytes (its gate column) per step,
// eliminating the warps-0/1 imbalance at the per-step barrier.
// ---------------------------------------------------------------------------
__global__ __launch_bounds__(256) void recur7(const float* __restrict__ R_s)
{
    __shared__ __align__(16) float hs2[2][64];
    __shared__ __align__(16) float xbuf[4][G_DIM];   // 4KB ring

    int t = threadIdx.x;
    int b = blockIdx.x;
    int l = t & 31, w = t >> 5;
    int gt = l >> 3;             // gate type: 0=z,1=i,2=f,3=o
    int base = l & 7;
    int dim = (w << 3) + base;   // owned hidden dim
    int col = gt * 64 + dim;     // column in R_s / xs

    ull R2[32];
#pragma unroll
    for (int i = 0; i < 32; i++)
        R2[i] = packf2(R_s[(2 * i) * G_DIM + col], R_s[(2 * i + 1) * G_DIM + col]);

    float alpha, ce, cr, c0;
    if (gt == 0)      { alpha = -2.f; ce = 0.f; cr = 2.f; c0 = -1.f; }  // tanh
    else if (gt == 1) { alpha =  1.f; ce = 1.f; cr = 0.f; c0 =  0.f; }  // exp
    else              { alpha = -1.f; ce = 0.f; cr = 1.f; c0 =  0.f; }  // sigmoid

    float cs = 0.f, ns = 1.f;
    if (t < 64) hs2[1][t] = 0.f;     // A(0) reads buffer 1

    const size_t BG = (size_t)B_DIM * G_DIM;
    const float* xsrc = g_xs + (size_t)b * G_DIM + t;   // this thread's column
    uint32_t xb_s = (uint32_t)__cvta_generic_to_shared(&xbuf[0][0]) + t * 4;

    // prime stages 0..2 (every thread loads its own 4B per stage)
#pragma unroll
    for (int p = 0; p < 3; p++) {
        cp_async4(xb_s + p * (G_DIM * 4), xsrc + (size_t)p * BG);
        cp_commit();
    }
    cp_wait2();        // stage 0 complete; stages 1,2 in flight
    __syncthreads();

    float* hout = g_h + (size_t)b * S_DIM * D_DIM;

    for (int s = 0; s < S_DIM; s++) {
        // ---- A(s): g = xbuf + hs(s-1) @ R_s[:,col] ----
        float gv = xbuf[s & 3][col];
        {
            const ulonglong2* h2 = reinterpret_cast<const ulonglong2*>(hs2[(s + 1) & 1]);
            ull a0 = 0, a1 = 0, a2 = 0, a3 = 0;
#pragma unroll
            for (int q = 0; q < 8; q++) {
                ulonglong2 u = h2[2 * q];
                ulonglong2 v = h2[2 * q + 1];
                ffma2(a0, u.x, R2[4 * q]);
                ffma2(a1, u.y, R2[4 * q + 1]);
                ffma2(a2, v.x, R2[4 * q + 2]);
                ffma2(a3, v.y, R2[4 * q + 3]);
            }
            a0 = addf2(a0, a1); a2 = addf2(a2, a3); a0 = addf2(a0, a2);
            float2 p = unpackf2(a0);
            gv += p.x + p.y;
        }
        float u = __expf(alpha * gv);
        float act = ce * u + cr * __fdividef(1.f, 1.f + u) + c0;

        // ---- B(s): intra-warp gate exchange + state update ----
        float z  = __shfl_sync(0xffffffffu, act, base);
        float ig = __shfl_sync(0xffffffffu, act, 8 + base);
        float f  = __shfl_sync(0xffffffffu, act, 16 + base);
        float o  = __shfl_sync(0xffffffffu, act, 24 + base);
        cs = f * cs + ig * z;
        ns = f * ns + ig;
        float h = __fdividef(o * cs, ns);
        if (l < 8) {
            hs2[s & 1][dim] = h;
            hout[s * D_DIM + dim] = h;     // stream raw h for projln
        }

        // ---- prefetch step s+3 into stage (s+3)&3 (own 4B); s+1 ready ----
        {
            int sn = (s + 3 < S_DIM) ? (s + 3) : (S_DIM - 1);
            cp_async4(xb_s + ((s + 3) & 3) * (G_DIM * 4), xsrc + (size_t)sn * BG);
            cp_commit();
            cp_wait2();    // pending <= {s+2, s+3} -> stage s+1 complete
        }
        __syncthreads();
    }
}

// ---------------------------------------------------------------------------
// Kernel 4: LN + k/v projections + im/fm logits. Occupancy bumped to 3 CTAs.
// ---------------------------------------------------------------------------
__global__ __launch_bounds__(256, 3) void projln(
    const float* __restrict__ Wk, const float* __restrict__ Wv,
    const float* __restrict__ ln_g, const float* __restrict__ ln_b,
    const float* __restrict__ wi, const float* __restrict__ bi_p,
    const float* __restrict__ wf, const float* __restrict__ bf_p)
{
    __shared__ __align__(16) float hsm[64][HPAD];
    __shared__ float lng[64], lnb[64], wis[64], wfs[64];
    int t = threadIdx.x;
    size_t row0 = (size_t)blockIdx.x * 64;

    {
        const float4* hg = reinterpret_cast<const float4*>(g_h + row0 * D_DIM);
#pragma unroll
        for (int i = 0; i < 4; i++) {
            int idx = t + i * 256;
            int row = idx >> 4, c4 = idx & 15;
            *reinterpret_cast<float4*>(&hsm[row][c4 * 4]) = hg[idx];
        }
    }
    if (t < 64) { lng[t] = ln_g[t]; lnb[t] = ln_b[t]; wis[t] = wi[t]; wfs[t] = wf[t]; }
    __syncthreads();

    {
        int row = t >> 2, q = t & 3;
        float s1 = 0.f, s2 = 0.f;
#pragma unroll
        for (int e4 = 0; e4 < 4; e4++) {
            float4 v = *reinterpret_cast<float4*>(&hsm[row][q * 16 + e4 * 4]);
            s1 += v.x + v.y + v.z + v.w;
            s2 += v.x * v.x + v.y * v.y + v.z * v.z + v.w * v.w;
        }
        s1 += __shfl_xor_sync(0xffffffffu, s1, 1);
        s2 += __shfl_xor_sync(0xffffffffu, s2, 1);
        s1 += __shfl_xor_sync(0xffffffffu, s1, 2);
        s2 += __shfl_xor_sync(0xffffffffu, s2, 2);
        float mu  = s1 * 0.015625f;
        float inv = rsqrtf(s2 * 0.015625f - mu * mu + 1e-5f);
#pragma unroll
        for (int e4 = 0; e4 < 4; e4++) {
            int c = q * 16 + e4 * 4;
            float4 v = *reinterpret_cast<float4*>(&hsm[row][c]);
            v.x = (v.x - mu) * inv * lng[c]     + lnb[c];
            v.y = (v.y - mu) * inv * lng[c + 1] + lnb[c + 1];
            v.z = (v.z - mu) * inv * lng[c + 2] + lnb[c + 2];
            v.w = (v.w - mu) * inv * lng[c + 3] + lnb[c + 3];
            *reinterpret_cast<float4*>(&hsm[row][c]) = v;
        }
    }
    __syncthreads();

    {
        float4* og = reinterpret_cast<float4*>(g_hso + row0 * D_DIM);
#pragma unroll
        for (int i = 0; i < 4; i++) {
            int idx = t + i * 256;
            int row = idx >> 4, c4 = idx & 15;
            og[idx] = *reinterpret_cast<float4*>(&hsm[row][c4 * 4]);
        }
    }

    if (t < 64) {
        float pi = bi_p[0], pf = bf_p[0];
#pragma unroll 8
        for (int d = 0; d < 64; d++) {
            float h = hsm[t][d];
            pi += h * wis[d];
            pf += h * wfs[d];
        }
        g_im[row0 + t] = __expf(pi);
        g_fm[row0 + t] = __fdividef(1.f, 1.f + __expf(-pf));
    }

    int rg = t >> 7;
    int col = t & 127;
    const float* Wsel = (col < 64) ? Wk : Wv;
    const int c = col & 63;
    ull W2[32];
#pragma unroll
    for (int i = 0; i < 32; i++)
        W2[i] = packf2(Wsel[(2 * i) * 64 + c], Wsel[(2 * i + 1) * 64 + c]);
    float scale = (col < 64) ? 0.125f : 1.f;
    float* outp = (col < 64) ? g_k : g_v;

    for (int r = 0; r < 32; r += 2) {
        int row = rg * 32 + r;
        ull a0 = 0, a1 = 0, b0 = 0, b1 = 0;
        const ulonglong2* h0 = reinterpret_cast<const ulonglong2*>(hsm[row]);
        const ulonglong2* h1 = reinterpret_cast<const ulonglong2*>(hsm[row + 1]);
#pragma unroll
        for (int q = 0; q < 16; q++) {
            ulonglong2 u = h0[q];
            ffma2(a0, u.x, W2[2 * q]);
            ffma2(a1, u.y, W2[2 * q + 1]);
            ulonglong2 v = h1[q];
            ffma2(b0, v.x, W2[2 * q]);
            ffma2(b1, v.y, W2[2 * q + 1]);
        }
        a0 = addf2(a0, a1); b0 = addf2(b0, b1);
        float2 fa = unpackf2(a0);
        float2 fb = unpackf2(b0);
        outp[(row0 + row) * 64 + c]     = (fa.x + fa.y) * scale;
        outp[(row0 + row + 1) * 64 + c] = (fb.x + fb.y) * scale;
    }
}

// ---------------------------------------------------------------------------
// Kernel 5: per-batch suffix-product scan + weighted sums + fusion gate.
// ---------------------------------------------------------------------------
__global__ __launch_bounds__(64) void scan2(
    const float* __restrict__ Wq,
    const float* __restrict__ Wo, const float* __restrict__ bo,
    const float* __restrict__ W_fuse, const float* __restrict__ b_fuse,
    float* __restrict__ out)
{
    __shared__ float hlast[64], qv[64], omv[64], hm[64];
    __shared__ float fmv[512], cp[512], av[512];

    int t = threadIdx.x;
    int b = blockIdx.x;
    const float* hso_b = g_hso + (size_t)b * S_DIM * D_DIM;

    hlast[t] = hso_b[511 * 64 + t];
    for (int s = t; s < S_DIM; s += 64) fmv[s] = g_fm[(size_t)b * S_DIM + s];
    __syncthreads();

    {
        float aq = 0.f, ao = bo[t];
#pragma unroll 8
        for (int d = 0; d < 64; d++) {
            float h = hlast[d];
            aq += h * Wq[d * 64 + t];
            ao += h * Wo[d * 64 + t];
        }
        qv[t] = aq;
        omv[t] = __fdividef(1.f, 1.f + __expf(-ao));
    }
    __syncthreads();

    if (t == 0) {
        float c = 1.f;
        cp[511] = 1.f;
        for (int s = 510; s >= 0; s--) { c *= fmv[s + 1]; cp[s] = c; }
    }
    __syncthreads();

    const float* kb = g_k + (size_t)b * S_DIM * D_DIM;
    for (int s = t; s < S_DIM; s += 64) {
        const float4* kr = reinterpret_cast<const float4*>(kb + s * 64);
        float kq = 0.f;
#pragma unroll
        for (int d4 = 0; d4 < 16; d4++) {
            float4 kv = kr[d4];
            kq += kv.x * qv[d4*4] + kv.y * qv[d4*4+1] + kv.z * qv[d4*4+2] + kv.w * qv[d4*4+3];
        }
        av[s] = g_im[(size_t)b * S_DIM + s] * cp[s] * kq;
    }
    __syncthreads();

    const float* vb = g_v + (size_t)b * S_DIM * D_DIM;
    float num = 0.f, den = 0.f;
#pragma unroll 4
    for (int s = 0; s < S_DIM; s++) {
        float a = av[s];
        num += a * vb[s * 64 + t];
        den += a;
    }
    den = fmaxf(fabsf(den), 1.f);
    hm[t] = omv[t] * num / den;
    __syncthreads();

    float gp = b_fuse[t];
#pragma unroll 8
    for (int r = 0; r < 64; r++) gp += hlast[r] * W_fuse[r * 64 + t];
#pragma unroll 8
    for (int r = 0; r < 64; r++) gp += hm[r] * W_fuse[(64 + r) * 64 + t];
    float gate = __fdividef(1.f, 1.f + __expf(-gp));
    out[b * 64 + t] = gate * hm[t] + (1.f - gate) * hlast[t];
}

// ---------------------------------------------------------------------------
extern "C" void kernel_launch(void* const* d_in, const int* in_sizes, int n_in,
                              void* d_out, int out_size) {
    const float* x      = (const float*)d_in[0];
    const float* W_in   = (const float*)d_in[1];
    const float* b_in   = (const float*)d_in[2];
    const float* W_s    = (const float*)d_in[3];
    const float* R_s    = (const float*)d_in[4];
    const float* b_s    = (const float*)d_in[5];
    const float* ln_g   = (const float*)d_in[6];
    const float* ln_b   = (const float*)d_in[7];
    const float* Wq     = (const float*)d_in[8];
    const float* Wk     = (const float*)d_in[9];
    const float* Wv     = (const float*)d_in[10];
    const float* wi     = (const float*)d_in[11];
    const float* bi     = (const float*)d_in[12];
    const float* wf     = (const float*)d_in[13];
    const float* bf     = (const float*)d_in[14];
    const float* Wo     = (const float*)d_in[15];
    const float* bo     = (const float*)d_in[16];
    const float* W_fuse = (const float*)d_in[17];
    const float* b_fuse = (const float*)d_in[18];
    float* out = (float*)d_out;

    combine_weights<<<IN_DIM + 1, G_DIM>>>(W_in, b_in, W_s, b_s);
    xs_gemm<<<(B_DIM * S_DIM) / TILE_R, 256>>>(x);
    recur7<<<B_DIM, 256>>>(R_s);
    projln<<<(B_DIM * S_DIM) / 64, 256>>>(Wk, Wv, ln_g, ln_b, wi, bi, wf, bf);
    scan2<<<B_DIM, 64>>>(Wq, Wo, bo, W_fuse, b_fuse, out);
}